// round 1
// baseline (speedup 1.0000x reference)
#include <cuda_runtime.h>
#include <cuda_bf16.h>

// CSPN propagation step:
//   out[b,0,y,x] = sum_{t=0..24} gw[b,t,y+2,x+2] * src_t(y+2-dy, x+2-dx)
// with dy=t/5, dx=t%5, src_t = h0 for t==12 else hn, zero outside [0,H)x[0,W).
//
// Shapes: gw (4, 25, 356, 1220) f32, hn/h0 (4, 1, 352, 1216) f32,
//         out (4, 1, 352, 1216) f32.

#define K 5
#define Hc 352
#define Wc 1216
#define Hp 356
#define Wp 1220
#define Bc 4

__global__ __launch_bounds__(256)
void cspn_kernel(const float* __restrict__ gw,
                 const float* __restrict__ hn,
                 const float* __restrict__ h0,
                 float* __restrict__ out)
{
    // one thread computes 2 adjacent x pixels
    const int WPAIRS = Wc / 2;                       // 608
    int idx = blockIdx.x * blockDim.x + threadIdx.x;
    const int total = Bc * Hc * WPAIRS;
    if (idx >= total) return;

    const int xp  = idx % WPAIRS;
    int rem       = idx / WPAIRS;
    const int y   = rem % Hc;
    const int b   = rem / Hc;
    const int x   = xp * 2;

    const size_t planeW = (size_t)Hp * Wp;           // 434320
    const float* wb = gw + (size_t)b * 25 * planeW
                         + (size_t)(y + 2) * Wp + (x + 2);
    const float* hb = hn + (size_t)b * Hc * Wc;
    const float* h0b = h0 + (size_t)b * Hc * Wc;

    float acc0 = 0.f, acc1 = 0.f;

    #pragma unroll
    for (int t = 0; t < 25; ++t) {
        const int dy = t / K;
        const int dx = t % K;
        // aligned 8B weight load (offset parity: even for even x)
        const float2 w2 = *reinterpret_cast<const float2*>(wb + (size_t)t * planeW);

        const int iy  = y + 2 - dy;      // [y-2, y+2]
        const int ix0 = x + 2 - dx;      // [x-2, x+2]
        const int ix1 = ix0 + 1;

        float v0 = 0.f, v1 = 0.f;
        if (t == 12) {
            // center tap: h0 at (y, x) — always in range
            v0 = __ldg(h0b + (size_t)y * Wc + x);
            v1 = __ldg(h0b + (size_t)y * Wc + x + 1);
        } else {
            const bool yok = (unsigned)iy < (unsigned)Hc;
            if (yok) {
                const float* row = hb + (size_t)iy * Wc;
                if ((unsigned)ix0 < (unsigned)Wc) v0 = __ldg(row + ix0);
                if ((unsigned)ix1 < (unsigned)Wc) v1 = __ldg(row + ix1);
            }
        }
        acc0 = fmaf(w2.x, v0, acc0);
        acc1 = fmaf(w2.y, v1, acc1);
    }

    float2 o;
    o.x = acc0;
    o.y = acc1;
    *reinterpret_cast<float2*>(out + (size_t)b * Hc * Wc + (size_t)y * Wc + x) = o;
}

extern "C" void kernel_launch(void* const* d_in, const int* in_sizes, int n_in,
                              void* d_out, int out_size)
{
    const float* gw = (const float*)d_in[0];
    const float* hn = (const float*)d_in[1];
    const float* h0 = (const float*)d_in[2];
    float* out = (float*)d_out;

    const int total = Bc * Hc * (Wc / 2);            // 856064 threads
    const int threads = 256;
    const int blocks = (total + threads - 1) / threads;
    cspn_kernel<<<blocks, threads>>>(gw, hn, h0, out);
}

// round 4
// speedup vs baseline: 1.1101x; 1.1101x over previous
#include <cuda_runtime.h>
#include <cuda_bf16.h>

// CSPN propagation step:
//   out[b,0,y,x] = sum_{t=0..24} gw[b,t,y+2,x+2] * src_t(y+2-t/5, x+2-t%5)
// src_t = h0 for t==12 (center), else hn; zero outside [0,H)x[0,W).
// gw (4,25,356,1220) f32, hn/h0 (4,1,352,1216) f32, out (4,1,352,1216) f32.

#define K 5
#define Hc 352
#define Wc 1216
#define Hp 356
#define Wp 1220
#define Bc 4

__global__ __launch_bounds__(256)
void cspn_kernel(const float* __restrict__ gw,
                 const float* __restrict__ hn,
                 const float* __restrict__ h0,
                 float* __restrict__ out)
{
    // one thread computes 4 adjacent x pixels
    const int WQ = Wc / 4;                           // 304
    int idx = blockIdx.x * blockDim.x + threadIdx.x;
    const int total = Bc * Hc * WQ;                  // 428032
    if (idx >= total) return;

    const int xq  = idx % WQ;
    int rem       = idx / WQ;
    const int y   = rem % Hc;
    const int b   = rem / Hc;
    const int x   = xq * 4;

    const size_t planeW = (size_t)Hp * Wp;           // 434320
    const float* wb  = gw + (size_t)b * 25 * planeW
                          + (size_t)(y + 2) * Wp + (x + 2);
    const float* hb  = hn + (size_t)b * Hc * Wc;
    const float* h0b = h0 + (size_t)b * Hc * Wc;

    float acc0 = 0.f, acc1 = 0.f, acc2 = 0.f, acc3 = 0.f;

    // center-tap h0 values (always in range, 16B aligned)
    const float4 c4 = *reinterpret_cast<const float4*>(h0b + (size_t)y * Wc + x);

    #pragma unroll
    for (int dy = 0; dy < K; ++dy) {
        const int iy = y + 2 - dy;                   // [y-2, y+2]
        const bool yok = (unsigned)iy < (unsigned)Hc;
        const float* row = hb + (size_t)iy * Wc;

        // load the 8-wide hn span [x-2, x+5] once for this tap row
        float v[8];
        #pragma unroll
        for (int k = 0; k < 8; ++k) {
            const int ix = x - 2 + k;
            v[k] = (yok && (unsigned)ix < (unsigned)Wc) ? __ldg(row + ix) : 0.f;
        }

        #pragma unroll
        for (int dx = 0; dx < K; ++dx) {
            const int t = dy * K + dx;
            const float* wp = wb + (size_t)t * planeW;
            // two aligned 8B weight loads (base offset even)
            const float2 wA = __ldg(reinterpret_cast<const float2*>(wp));
            const float2 wB = __ldg(reinterpret_cast<const float2*>(wp + 2));

            float s0, s1, s2, s3;
            if (t == 12) {
                s0 = c4.x; s1 = c4.y; s2 = c4.z; s3 = c4.w;
            } else {
                const int base = 4 - dx;             // v index for pixel 0
                s0 = v[base + 0];
                s1 = v[base + 1];
                s2 = v[base + 2];
                s3 = v[base + 3];
            }
            acc0 = fmaf(wA.x, s0, acc0);
            acc1 = fmaf(wA.y, s1, acc1);
            acc2 = fmaf(wB.x, s2, acc2);
            acc3 = fmaf(wB.y, s3, acc3);
        }
    }

    float4 o;
    o.x = acc0; o.y = acc1; o.z = acc2; o.w = acc3;
    *reinterpret_cast<float4*>(out + (size_t)b * Hc * Wc + (size_t)y * Wc + x) = o;
}

extern "C" void kernel_launch(void* const* d_in, const int* in_sizes, int n_in,
                              void* d_out, int out_size)
{
    const float* gw = (const float*)d_in[0];
    const float* hn = (const float*)d_in[1];
    const float* h0 = (const float*)d_in[2];
    float* out = (float*)d_out;

    const int total = Bc * Hc * (Wc / 4);            // 428032 threads
    const int threads = 256;
    const int blocks = (total + threads - 1) / threads;
    cspn_kernel<<<blocks, threads>>>(gw, hn, h0, out);
}